// round 5
// baseline (speedup 1.0000x reference)
#include <cuda_runtime.h>

// Problem constants (fixed by the reference setup)
#define N_USERS  50000
#define N_NODES  200000   // 50000 + 150000
#define D        64
#define NEDGE    3200000
#define BATCH    4096
#define NWORDS   ((N_NODES + 31) / 32)
#define OUT_BLOCKS 148

// ---------------- scratch (static device globals; no allocation) ------------
__device__ float    g_vsrc[D];
__device__ float    g_vdst[D];
__device__ float    g_bsrc;
__device__ float    g_bdst;
__device__ int      g_is64;                 // indices dtype flag (1 => int64)
__device__ float    g_sdst[N_NODES];        // only flagged entries valid
__device__ int      g_flag[N_NODES];        // dedup claim (cleared by k_out)
__device__ unsigned g_flagbits[NWORDS];     // 25 KB bitmask for k_edge filter
__device__ float    g_denom[N_NODES];
__device__ float    g_zacc[(size_t)N_NODES * D];   // only needed rows touched
__device__ float    g_hout[(size_t)N_NODES * D];   // only needed rows touched
__device__ int      g_needed[2 * BATCH];
__device__ int      g_nneeded;

__device__ __forceinline__ const float* frow(int n, const float* ue, const float* ee) {
    return (n < N_USERS) ? (ue + (size_t)n * D) : (ee + (size_t)(n - N_USERS) * D);
}

// ---------------- K0: fold W_att/a into two 64-vectors; reset counters ------
__global__ void k_prep(const float* __restrict__ Watt, const float* __restrict__ Wattb,
                       const float* __restrict__ a, const int* __restrict__ idx_raw) {
    int t = threadIdx.x;
    if (t < D) {
        float vs = 0.f, vd = 0.f;
        #pragma unroll 8
        for (int j = 0; j < D; j++) {
            float w = Watt[t * D + j];
            vs += w * a[j];
            vd += w * a[D + j];
        }
        g_vsrc[t] = vs;
        g_vdst[t] = vd;
    } else if (t == 64) {
        float b1 = 0.f, b2 = 0.f;
        for (int j = 0; j < D; j++) { b1 += Wattb[j] * a[j]; b2 += Wattb[j] * a[D + j]; }
        g_bsrc = b1;
        g_bdst = b2;
        g_nneeded = 0;
    } else if (t == 65) {
        // int64 detection: node ids < 2^31, so as int32 words every odd word == 0.
        int orv = 0;
        for (int j = 1; j < 128; j += 2) orv |= idx_raw[j];
        g_is64 = (orv == 0) ? 1 : 0;
    }
}

// ---- K1: flag needed dst nodes (dedup), compute s_dst, zero accumulators ---
__global__ void k_flag(const int* __restrict__ uid, const int* __restrict__ iid,
                       const float* __restrict__ ue, const float* __restrict__ ee) {
    __shared__ float vd[D];
    if (threadIdx.x < D) vd[threadIdx.x] = g_vdst[threadIdx.x];
    __syncthreads();

    int i = blockIdx.x * blockDim.x + threadIdx.x;
    if (i >= 2 * BATCH) return;
    int node = (i < BATCH) ? uid[i] : (N_USERS + iid[i - BATCH]);
    if (atomicExch(&g_flag[node], 1) == 0) {
        int p = atomicAdd(&g_nneeded, 1);
        g_needed[p] = node;
        atomicOr(&g_flagbits[node >> 5], 1u << (node & 31));
        g_denom[node] = 0.f;
        const float4* f4 = (const float4*)frow(node, ue, ee);
        float4* z = (float4*)&g_zacc[(size_t)node * D];
        float sd = 0.f;
        #pragma unroll
        for (int q = 0; q < 16; q++) {
            float4 v = f4[q];
            sd += v.x * vd[4*q] + v.y * vd[4*q+1] + v.z * vd[4*q+2] + v.w * vd[4*q+3];
            z[q] = make_float4(0.f, 0.f, 0.f, 0.f);
        }
        g_sdst[node] = sd + g_bdst;
    }
}

// ---- warp-cooperative survivor processing (s_src computed from the row) ----
__device__ __forceinline__ void process_survivors(
    unsigned m, int s, int d, int lane, float bs,
    const float* __restrict__ ue, const float* __restrict__ ee,
    const float* __restrict__ vs)
{
    while (m) {
        int sl = __ffs(m) - 1;
        m &= m - 1;
        int es = __shfl_sync(0xffffffffu, s, sl);
        int ed = __shfl_sync(0xffffffffu, d, sl);
        const float* f = frow(es, ue, ee);
        float f0 = f[lane], f1 = f[lane + 32];
        float p = f0 * vs[lane] + f1 * vs[lane + 32];
        #pragma unroll
        for (int off = 16; off; off >>= 1) p += __shfl_xor_sync(0xffffffffu, p, off);
        float x = p + bs + g_sdst[ed];
        x = (x > 0.f) ? x : 0.2f * x;       // leaky_relu(0.2)
        float w = __expf(x);                // global-max shift dropped (|x| tiny)
        float* zr = &g_zacc[(size_t)ed * D];
        atomicAdd(&zr[lane],      w * f0);
        atomicAdd(&zr[lane + 32], w * f1);
        if (lane == 0) atomicAdd(&g_denom[ed], w);
    }
}

// ---------------- K2: single edge pass (4 edges/thread) ---------------------
__global__ void k_edge(const int* __restrict__ idx,
                       const float* __restrict__ ue, const float* __restrict__ ee) {
    __shared__ float vs[D];
    if (threadIdx.x < D) vs[threadIdx.x] = g_vsrc[threadIdx.x];
    __syncthreads();

    int t = blockIdx.x * blockDim.x + threadIdx.x;
    int lane = threadIdx.x & 31;
    float bs = g_bsrc;

    int s[4] = {0, 0, 0, 0}, d[4] = {0, 0, 0, 0};
    bool ok[4] = {false, false, false, false};
    long long e0 = 4LL * t;

    if (e0 + 3 < NEDGE) {
        if (g_is64) {
            const long long* idx64 = (const long long*)idx;
            ulonglong2 da = __ldcs(((const ulonglong2*)(idx64 + NEDGE)) + 2 * t);
            ulonglong2 db = __ldcs(((const ulonglong2*)(idx64 + NEDGE)) + 2 * t + 1);
            d[0] = (int)da.x; d[1] = (int)da.y; d[2] = (int)db.x; d[3] = (int)db.y;
            #pragma unroll
            for (int q = 0; q < 4; q++) {
                ok[q] = (g_flagbits[d[q] >> 5] >> (d[q] & 31)) & 1u;
                if (ok[q]) s[q] = (int)__ldcs(idx64 + e0 + q);
            }
        } else {
            int4 dd = __ldcs(((const int4*)(idx + NEDGE)) + t);
            d[0] = dd.x; d[1] = dd.y; d[2] = dd.z; d[3] = dd.w;
            #pragma unroll
            for (int q = 0; q < 4; q++) {
                ok[q] = (g_flagbits[d[q] >> 5] >> (d[q] & 31)) & 1u;
                if (ok[q]) s[q] = __ldcs(idx + e0 + q);
            }
        }
    } else if (e0 < NEDGE) {
        // generic tail (unused for NEDGE % 4 == 0; kept for safety)
        int cnt = (int)(NEDGE - e0);
        for (int q = 0; q < 4; q++) {
            if (q < cnt) {
                d[q] = g_is64 ? (int)((const long long*)idx)[(size_t)NEDGE + e0 + q]
                              : idx[(size_t)NEDGE + e0 + q];
                ok[q] = (g_flagbits[d[q] >> 5] >> (d[q] & 31)) & 1u;
                if (ok[q]) s[q] = g_is64 ? (int)((const long long*)idx)[e0 + q]
                                         : idx[e0 + q];
            }
        }
    }

    #pragma unroll
    for (int q = 0; q < 4; q++) {
        unsigned m = __ballot_sync(0xffffffffu, ok[q]);
        process_survivors(m, s[q], d[q], lane, bs, ue, ee, vs);
    }
}

// ---- K3: persistent epilogue (h_neigh, h_out, normalize, state reset) ------
__global__ void __launch_bounds__(256) k_out(
        const float* __restrict__ ue, const float* __restrict__ ee,
        const float* __restrict__ W1, const float* __restrict__ W1b,
        const float* __restrict__ W2, const float* __restrict__ W2b) {
    __shared__ float W1s[D * D];
    __shared__ float W2s[D * D];
    __shared__ float zb[8][D];
    __shared__ float pb[8][D];

    for (int i = threadIdx.x; i < D * D; i += blockDim.x) {
        W1s[i] = W1[i];
        W2s[i] = W2[i];
    }
    __syncthreads();

    int wid  = threadIdx.x >> 5;
    int lane = threadIdx.x & 31;
    int nn   = g_nneeded;

    for (int wi = (blockIdx.x << 3) + wid; wi < nn; wi += (gridDim.x << 3)) {
        int n = g_needed[wi];
        float den = g_denom[n];
        float inv = 1.0f / (den + 1e-9f);
        float ca  = den * inv;             // sum of alphas (multiplies the W1 bias)

        const float* zr = &g_zacc[(size_t)n * D];
        zb[wid][lane]      = zr[lane]      * inv;
        zb[wid][lane + 32] = zr[lane + 32] * inv;
        __syncwarp();

        float hn0 = W1b[lane] * ca, hn1 = W1b[lane + 32] * ca;
        #pragma unroll 8
        for (int k = 0; k < D; k++) {
            float zk = zb[wid][k];
            hn0 += zk * W1s[k * D + lane];
            hn1 += zk * W1s[k * D + lane + 32];
        }

        const float* f = frow(n, ue, ee);
        float f0 = f[lane], f1 = f[lane + 32];
        float s0 = f0 + hn0, s1 = f1 + hn1;
        float p0 = f0 * hn0, p1 = f1 * hn1;
        pb[wid][lane]      = p0;
        pb[wid][lane + 32] = p1;
        __syncwarp();

        float q0 = W2b[lane], q1 = W2b[lane + 32];
        #pragma unroll 8
        for (int k = 0; k < D; k++) {
            float pk = pb[wid][k];
            q0 += pk * W2s[k * D + lane];
            q1 += pk * W2s[k * D + lane + 32];
        }
        float o0 = s0 + q0, o1 = s1 + q1;
        o0 = (o0 > 0.f) ? o0 : 0.2f * o0;
        o1 = (o1 > 0.f) ? o1 : 0.2f * o1;

        float sq = o0 * o0 + o1 * o1;
        #pragma unroll
        for (int off = 16; off; off >>= 1) sq += __shfl_xor_sync(0xffffffffu, sq, off);
        float sc = 1.0f / fmaxf(sqrtf(sq), 1e-12f);

        g_hout[(size_t)n * D + lane]      = o0 * sc;
        g_hout[(size_t)n * D + lane + 32] = o1 * sc;

        // reset per-replay state for the next graph replay
        if (lane == 0) {
            g_flag[n] = 0;
            g_flagbits[n >> 5] = 0u;   // racy but all writers store 0 — benign
        }
        __syncwarp();
    }
}

// ---------------- K4: final batched row dots --------------------------------
__global__ void k_final(const int* __restrict__ uid, const int* __restrict__ iid,
                        const float* __restrict__ ue, const float* __restrict__ ee,
                        float* __restrict__ out) {
    int wi = (blockIdx.x << 2) + (threadIdx.x >> 5);
    if (wi >= BATCH) return;
    int lane = threadIdx.x & 31;
    int u  = uid[wi];
    int it = iid[wi];
    const float* fu = ue + (size_t)u * D;
    const float* fi = ee + (size_t)it * D;
    const float* hu = &g_hout[(size_t)u * D];
    const float* hi = &g_hout[(size_t)(N_USERS + it) * D];
    float acc = fu[lane] * fi[lane] + fu[lane + 32] * fi[lane + 32]
              + hu[lane] * hi[lane] + hu[lane + 32] * hi[lane + 32];
    #pragma unroll
    for (int off = 16; off; off >>= 1) acc += __shfl_xor_sync(0xffffffffu, acc, off);
    if (lane == 0) out[wi] = acc;
}

// ---------------- launch ----------------------------------------------------
extern "C" void kernel_launch(void* const* d_in, const int* in_sizes, int n_in,
                              void* d_out, int out_size) {
    const int* indices = (const int*)d_in[0];
    const int* uid     = (const int*)d_in[1];
    const int* iid     = (const int*)d_in[2];
    // num_nodes is a scalar input if present; detect and skip it.
    int base = 3;
    if (n_in >= 13 && in_sizes[3] == 1) base = 4;
    const float* ue    = (const float*)d_in[base + 0];
    const float* ee    = (const float*)d_in[base + 1];
    const float* Watt  = (const float*)d_in[base + 2];
    const float* Wattb = (const float*)d_in[base + 3];
    const float* W1    = (const float*)d_in[base + 4];
    const float* W1b   = (const float*)d_in[base + 5];
    const float* W2    = (const float*)d_in[base + 6];
    const float* W2b   = (const float*)d_in[base + 7];
    const float* a     = (const float*)d_in[base + 8];
    float* out = (float*)d_out;

    k_prep <<<1, 128>>>(Watt, Wattb, a, indices);
    k_flag <<<(2 * BATCH + 255) / 256, 256>>>(uid, iid, ue, ee);
    k_edge <<<(NEDGE / 4 + 255) / 256, 256>>>(indices, ue, ee);
    k_out  <<<OUT_BLOCKS, 256>>>(ue, ee, W1, W1b, W2, W2b);
    k_final<<<(BATCH + 3) / 4, 128>>>(uid, iid, ue, ee, out);
}

// round 7
// speedup vs baseline: 1.0714x; 1.0714x over previous
#include <cuda_runtime.h>

// Problem constants (fixed by the reference setup)
#define N_USERS  50000
#define N_NODES  200000   // 50000 + 150000
#define D        64
#define NEDGE    3200000
#define BATCH    4096
#define NWORDS   ((N_NODES + 31) / 32)
#define OUT_BLOCKS 148

// ---------------- scratch (static device globals; no allocation) ------------
__device__ float    g_vsrc[D];
__device__ float    g_vdst[D];
__device__ float    g_bsrc;
__device__ float    g_bdst;
__device__ int      g_is64;                 // indices dtype flag (1 => int64)
__device__ float    g_sdst[N_NODES];        // only flagged entries valid
__device__ int      g_flag[N_NODES];        // dedup claim (cleared by k_out)
__device__ unsigned g_flagbits[NWORDS];     // 25 KB bitmask for k_edge filter
__device__ float    g_denom[N_NODES];
__device__ float    g_zacc[(size_t)N_NODES * D];   // only needed rows touched
__device__ float    g_hout[(size_t)N_NODES * D];   // only needed rows touched
__device__ int      g_needed[2 * BATCH];
__device__ int      g_nneeded;

__device__ __forceinline__ const float* frow(int n, const float* ue, const float* ee) {
    return (n < N_USERS) ? (ue + (size_t)n * D) : (ee + (size_t)(n - N_USERS) * D);
}

// ---------------- K0: fold W_att/a into two 64-vectors; reset counters ------
__global__ void k_prep(const float* __restrict__ Watt, const float* __restrict__ Wattb,
                       const float* __restrict__ a, const int* __restrict__ idx_raw) {
    int t = threadIdx.x;
    if (t < D) {
        float vs = 0.f, vd = 0.f;
        #pragma unroll 8
        for (int j = 0; j < D; j++) {
            float w = Watt[t * D + j];
            vs += w * a[j];
            vd += w * a[D + j];
        }
        g_vsrc[t] = vs;
        g_vdst[t] = vd;
    } else if (t == 64) {
        float b1 = 0.f, b2 = 0.f;
        for (int j = 0; j < D; j++) { b1 += Wattb[j] * a[j]; b2 += Wattb[j] * a[D + j]; }
        g_bsrc = b1;
        g_bdst = b2;
        g_nneeded = 0;
    } else if (t == 65) {
        // int64 detection: node ids < 2^31, so as int32 words every odd word == 0.
        int orv = 0;
        for (int j = 1; j < 128; j += 2) orv |= idx_raw[j];
        g_is64 = (orv == 0) ? 1 : 0;
    }
}

// ---- K1: flag needed dst nodes (dedup), compute s_dst, zero accumulators ---
__global__ void k_flag(const int* __restrict__ uid, const int* __restrict__ iid,
                       const float* __restrict__ ue, const float* __restrict__ ee) {
    __shared__ float vd[D];
    if (threadIdx.x < D) vd[threadIdx.x] = g_vdst[threadIdx.x];
    __syncthreads();

    int i = blockIdx.x * blockDim.x + threadIdx.x;
    if (i >= 2 * BATCH) return;
    int node = (i < BATCH) ? uid[i] : (N_USERS + iid[i - BATCH]);
    if (atomicExch(&g_flag[node], 1) == 0) {
        int p = atomicAdd(&g_nneeded, 1);
        g_needed[p] = node;
        atomicOr(&g_flagbits[node >> 5], 1u << (node & 31));
        g_denom[node] = 0.f;
        const float4* f4 = (const float4*)frow(node, ue, ee);
        float4* z = (float4*)&g_zacc[(size_t)node * D];
        float sd = 0.f;
        #pragma unroll
        for (int q = 0; q < 16; q++) {
            float4 v = f4[q];
            sd += v.x * vd[4*q] + v.y * vd[4*q+1] + v.z * vd[4*q+2] + v.w * vd[4*q+3];
            z[q] = make_float4(0.f, 0.f, 0.f, 0.f);
        }
        g_sdst[node] = sd + g_bdst;
    }
}

// ---- warp-cooperative survivor processing (s_src computed from the row) ----
__device__ __forceinline__ void process_survivors(
    unsigned m, int s, int d, int lane, float bs,
    const float* __restrict__ ue, const float* __restrict__ ee,
    const float* __restrict__ vs)
{
    while (m) {
        int sl = __ffs(m) - 1;
        m &= m - 1;
        int es = __shfl_sync(0xffffffffu, s, sl);
        int ed = __shfl_sync(0xffffffffu, d, sl);
        const float* f = frow(es, ue, ee);
        float f0 = f[lane], f1 = f[lane + 32];
        float p = f0 * vs[lane] + f1 * vs[lane + 32];
        #pragma unroll
        for (int off = 16; off; off >>= 1) p += __shfl_xor_sync(0xffffffffu, p, off);
        float x = p + bs + g_sdst[ed];
        x = (x > 0.f) ? x : 0.2f * x;       // leaky_relu(0.2)
        float w = __expf(x);                // global-max shift dropped (|x| tiny)
        float* zr = &g_zacc[(size_t)ed * D];
        atomicAdd(&zr[lane],      w * f0);
        atomicAdd(&zr[lane + 32], w * f1);
        if (lane == 0) atomicAdd(&g_denom[ed], w);
    }
}

// ---------------- K2: single edge pass (8 edges/thread) ---------------------
__global__ void k_edge(const int* __restrict__ idx,
                       const float* __restrict__ ue, const float* __restrict__ ee) {
    __shared__ float vs[D];
    if (threadIdx.x < D) vs[threadIdx.x] = g_vsrc[threadIdx.x];
    __syncthreads();

    int t = blockIdx.x * blockDim.x + threadIdx.x;
    int lane = threadIdx.x & 31;
    float bs = g_bsrc;

    int s[8], d[8];
    bool ok[8];
    #pragma unroll
    for (int q = 0; q < 8; q++) { s[q] = 0; d[q] = 0; ok[q] = false; }
    long long e0 = 8LL * t;

    if (e0 + 7 < NEDGE) {
        if (g_is64) {
            const long long* idx64 = (const long long*)idx;
            const ulonglong2* dq = (const ulonglong2*)(idx64 + NEDGE);
            #pragma unroll
            for (int j = 0; j < 4; j++) {
                ulonglong2 dd = __ldcs(dq + 4 * t + j);
                d[2*j]   = (int)dd.x;
                d[2*j+1] = (int)dd.y;
            }
            #pragma unroll
            for (int q = 0; q < 8; q++) {
                ok[q] = (g_flagbits[d[q] >> 5] >> (d[q] & 31)) & 1u;
                if (ok[q]) s[q] = (int)__ldcs(idx64 + e0 + q);
            }
        } else {
            const int4* dq = (const int4*)(idx + NEDGE);
            #pragma unroll
            for (int j = 0; j < 2; j++) {
                int4 dd = __ldcs(dq + 2 * t + j);
                d[4*j]   = dd.x; d[4*j+1] = dd.y; d[4*j+2] = dd.z; d[4*j+3] = dd.w;
            }
            #pragma unroll
            for (int q = 0; q < 8; q++) {
                ok[q] = (g_flagbits[d[q] >> 5] >> (d[q] & 31)) & 1u;
                if (ok[q]) s[q] = __ldcs(idx + e0 + q);
            }
        }
    } else if (e0 < NEDGE) {
        int cnt = (int)(NEDGE - e0);
        for (int q = 0; q < 8; q++) {
            if (q < cnt) {
                d[q] = g_is64 ? (int)((const long long*)idx)[(size_t)NEDGE + e0 + q]
                              : idx[(size_t)NEDGE + e0 + q];
                ok[q] = (g_flagbits[d[q] >> 5] >> (d[q] & 31)) & 1u;
                if (ok[q]) s[q] = g_is64 ? (int)((const long long*)idx)[e0 + q]
                                         : idx[e0 + q];
            }
        }
    }

    #pragma unroll
    for (int q = 0; q < 8; q++) {
        unsigned m = __ballot_sync(0xffffffffu, ok[q]);
        process_survivors(m, s[q], d[q], lane, bs, ue, ee, vs);
    }
}

// ---- 64x64 GEMV over a 4-node tile; src is [t*16+k4] float4 in smem --------
__device__ __forceinline__ void gemv64x4(const float* __restrict__ Ws,
                                         const float4* __restrict__ src,
                                         float a0[4], float a1[4], int lane) {
    #pragma unroll
    for (int k4 = 0; k4 < 16; k4++) {
        float4 z0 = src[0 * 16 + k4];
        float4 z1 = src[1 * 16 + k4];
        float4 z2 = src[2 * 16 + k4];
        float4 z3 = src[3 * 16 + k4];
        #define GSTEP(C, Q) { \
            int k = k4 * 4 + (Q); \
            float w0 = Ws[k * D + lane]; \
            float w1 = Ws[k * D + lane + 32]; \
            a0[0] += z0.C * w0;  a1[0] += z0.C * w1; \
            a0[1] += z1.C * w0;  a1[1] += z1.C * w1; \
            a0[2] += z2.C * w0;  a1[2] += z2.C * w1; \
            a0[3] += z3.C * w0;  a1[3] += z3.C * w1; }
        GSTEP(x, 0) GSTEP(y, 1) GSTEP(z, 2) GSTEP(w, 3)
        #undef GSTEP
    }
}

// ---- K3: register-tiled epilogue: 4 nodes per warp per iteration -----------
__global__ void __launch_bounds__(256) k_out(
        const float* __restrict__ ue, const float* __restrict__ ee,
        const float* __restrict__ W1, const float* __restrict__ W1b,
        const float* __restrict__ W2, const float* __restrict__ W2b) {
    __shared__ float W1s[D * D];
    __shared__ float W2s[D * D];
    __shared__ float4 buf[8][64];     // per-warp: z tile, then reused as p tile

    for (int i = threadIdx.x; i < D * D; i += blockDim.x) {
        W1s[i] = W1[i];
        W2s[i] = W2[i];
    }
    __syncthreads();

    int wid  = threadIdx.x >> 5;
    int lane = threadIdx.x & 31;
    float w1b0 = W1b[lane], w1b1 = W1b[lane + 32];
    float w2b0 = W2b[lane], w2b1 = W2b[lane + 32];
    int nn   = g_nneeded;
    int step = (int)gridDim.x * 8 * 4;

    for (int wi = ((int)blockIdx.x * 8 + wid) * 4; wi < nn; wi += step) {
        int nv = nn - wi; if (nv > 4) nv = 4;
        int myn = 0; float myden = 0.f;
        if (lane < nv) { myn = g_needed[wi + lane]; myden = g_denom[myn]; }

        int n_[4]; float inv_[4], ca_[4];
        #pragma unroll
        for (int t = 0; t < 4; t++) {
            n_[t] = __shfl_sync(0xffffffffu, myn, t);
            float dt = __shfl_sync(0xffffffffu, myden, t);
            float iv = 1.0f / (dt + 1e-9f);
            inv_[t] = iv;
            ca_[t]  = dt * iv;
        }

        // stage z (scaled by inv) as float4 tiles: buf[wid][t*16 + c4]
        #pragma unroll
        for (int j = 0; j < 2; j++) {
            int fi = j * 32 + lane;
            int t  = fi >> 4;
            int c4 = fi & 15;
            const float4* zr4 = (const float4*)(g_zacc + (size_t)n_[t] * D);
            float4 v = zr4[c4];
            float iv = inv_[t];
            v.x *= iv; v.y *= iv; v.z *= iv; v.w *= iv;
            buf[wid][t * 16 + c4] = v;
        }
        __syncwarp();

        // GEMV1: hn = z@W1 + ca*b1
        float a0[4], a1[4];
        #pragma unroll
        for (int t = 0; t < 4; t++) { a0[t] = w1b0 * ca_[t]; a1[t] = w1b1 * ca_[t]; }
        gemv64x4(W1s, &buf[wid][0], a0, a1, lane);
        __syncwarp();

        // elementwise: s = f + hn ; p = f * hn (p staged into buf)
        float s0[4], s1[4];
        float* pw = (float*)&buf[wid][0];
        #pragma unroll
        for (int t = 0; t < 4; t++) {
            const float* f = frow(n_[t], ue, ee);
            float f0 = f[lane], f1 = f[lane + 32];
            s0[t] = f0 + a0[t];
            s1[t] = f1 + a1[t];
            pw[t * D + lane]      = f0 * a0[t];
            pw[t * D + lane + 32] = f1 * a1[t];
        }
        __syncwarp();

        // GEMV2: q = p@W2 + b2
        float b0[4], b1[4];
        #pragma unroll
        for (int t = 0; t < 4; t++) { b0[t] = w2b0; b1[t] = w2b1; }
        gemv64x4(W2s, &buf[wid][0], b0, b1, lane);

        // leaky relu + L2 normalize + store + state reset
        #pragma unroll
        for (int t = 0; t < 4; t++) {
            float o0 = s0[t] + b0[t], o1 = s1[t] + b1[t];
            o0 = (o0 > 0.f) ? o0 : 0.2f * o0;
            o1 = (o1 > 0.f) ? o1 : 0.2f * o1;
            float sq = o0 * o0 + o1 * o1;
            #pragma unroll
            for (int off = 16; off; off >>= 1) sq += __shfl_xor_sync(0xffffffffu, sq, off);
            float sc = 1.0f / fmaxf(sqrtf(sq), 1e-12f);
            if (t < nv) {
                g_hout[(size_t)n_[t] * D + lane]      = o0 * sc;
                g_hout[(size_t)n_[t] * D + lane + 32] = o1 * sc;
            }
        }
        if (lane < nv) {
            g_flag[myn] = 0;
            g_flagbits[myn >> 5] = 0u;   // racy but all writers store 0 — benign
        }
        __syncwarp();
    }
}

// ---------------- K4: final batched row dots --------------------------------
__global__ void k_final(const int* __restrict__ uid, const int* __restrict__ iid,
                        const float* __restrict__ ue, const float* __restrict__ ee,
                        float* __restrict__ out) {
    int wi = (blockIdx.x << 2) + (threadIdx.x >> 5);
    if (wi >= BATCH) return;
    int lane = threadIdx.x & 31;
    int u  = uid[wi];
    int it = iid[wi];
    const float* fu = ue + (size_t)u * D;
    const float* fi = ee + (size_t)it * D;
    const float* hu = &g_hout[(size_t)u * D];
    const float* hi = &g_hout[(size_t)(N_USERS + it) * D];
    float acc = fu[lane] * fi[lane] + fu[lane + 32] * fi[lane + 32]
              + hu[lane] * hi[lane] + hu[lane + 32] * hi[lane + 32];
    #pragma unroll
    for (int off = 16; off; off >>= 1) acc += __shfl_xor_sync(0xffffffffu, acc, off);
    if (lane == 0) out[wi] = acc;
}

// ---------------- launch ----------------------------------------------------
extern "C" void kernel_launch(void* const* d_in, const int* in_sizes, int n_in,
                              void* d_out, int out_size) {
    const int* indices = (const int*)d_in[0];
    const int* uid     = (const int*)d_in[1];
    const int* iid     = (const int*)d_in[2];
    // num_nodes is a scalar input if present; detect and skip it.
    int base = 3;
    if (n_in >= 13 && in_sizes[3] == 1) base = 4;
    const float* ue    = (const float*)d_in[base + 0];
    const float* ee    = (const float*)d_in[base + 1];
    const float* Watt  = (const float*)d_in[base + 2];
    const float* Wattb = (const float*)d_in[base + 3];
    const float* W1    = (const float*)d_in[base + 4];
    const float* W1b   = (const float*)d_in[base + 5];
    const float* W2    = (const float*)d_in[base + 6];
    const float* W2b   = (const float*)d_in[base + 7];
    const float* a     = (const float*)d_in[base + 8];
    float* out = (float*)d_out;

    k_prep <<<1, 128>>>(Watt, Wattb, a, indices);
    k_flag <<<(2 * BATCH + 255) / 256, 256>>>(uid, iid, ue, ee);
    k_edge <<<(NEDGE / 8 + 255) / 256, 256>>>(indices, ue, ee);
    k_out  <<<OUT_BLOCKS, 256>>>(ue, ee, W1, W1b, W2, W2b);
    k_final<<<(BATCH + 3) / 4, 128>>>(uid, iid, ue, ee, out);
}